// round 1
// baseline (speedup 1.0000x reference)
#include <cuda_runtime.h>
#include <cuda_bf16.h>
#include <mma.h>
#include <math.h>

using namespace nvcuda;

// Problem constants
constexpr int B_ = 8;
constexpr int T_ = 2048;
constexpr int C_ = 1024;
constexpr int M_ROWS = B_ * T_;      // 16384
constexpr int N_QKV  = 3 * C_;       // 3072

// GEMM tiling
constexpr int BM = 64;
constexpr int BN = 64;
constexpr int BK = 32;

// Scratch (device globals: allocation-free per harness rules)
__device__ float g_qkv[(size_t)M_ROWS * N_QKV];   // [B*T, 3C]
__device__ float g_S[(size_t)B_ * T_ * T_];       // [B, T, T]
__device__ float g_O[(size_t)M_ROWS * C_];        // [B*T, C]

// ---------------------------------------------------------------------------
// Generic tf32 WMMA GEMM: C = alpha * A @ B (or A @ B^T when TRANS_B)
// A: [M,K] row-major. B: [K,N] row-major (TRANS_B=0) or [N,K] row-major (=1).
// CAUSAL: 0 = none, 1 = skip blocks strictly above diagonal (score GEMM),
//         2 = limit K-loop to <= m0+BM (P@V GEMM; A cols > row are zero).
// ---------------------------------------------------------------------------
template <bool TRANS_B, int CAUSAL>
__global__ void __launch_bounds__(128)
gemm_tf32_kernel(const float* __restrict__ Ag, const float* __restrict__ Bg,
                 float* __restrict__ Cg,
                 int M, int N, int K, int lda, int ldb, int ldc,
                 long long sA, long long sB, long long sC, float alpha)
{
    const long long bz = blockIdx.z;
    const float* A  = Ag + bz * sA;
    const float* Bp = Bg + bz * sB;
    float*       Cp = Cg + bz * sC;

    const int m0 = blockIdx.y * BM;
    const int n0 = blockIdx.x * BN;

    if (CAUSAL == 1 && n0 > m0 + BM - 1) return;   // fully above diagonal
    int kend = K;
    if (CAUSAL == 2) kend = min(K, m0 + BM);       // rest of A-row is zero

    __shared__ float As[BM][BK + 4];
    __shared__ float Bs[TRANS_B ? (BN * (BK + 4)) : (BK * (BN + 4))];

    const int tid  = threadIdx.x;
    const int warp = tid >> 5;
    const int wm   = (warp >> 1) * 32;   // warp row offset in tile
    const int wn   = (warp & 1) * 32;    // warp col offset in tile

    wmma::fragment<wmma::accumulator, 16, 16, 8, float> acc[2][2];
    #pragma unroll
    for (int i = 0; i < 2; i++)
        #pragma unroll
        for (int j = 0; j < 2; j++)
            wmma::fill_fragment(acc[i][j], 0.0f);

    for (int k0 = 0; k0 < kend; k0 += BK) {
        // --- load A tile: 64x32, float4 per thread iter ---
        #pragma unroll
        for (int i = tid; i < BM * BK / 4; i += 128) {
            int r = i >> 3, c = (i & 7) * 4;
            *(float4*)&As[r][c] =
                *(const float4*)&A[(size_t)(m0 + r) * lda + k0 + c];
        }
        // --- load B tile ---
        if constexpr (TRANS_B) {
            // B is [N,K] row-major; tile rows n0..n0+63, cols k0..k0+31
            #pragma unroll
            for (int i = tid; i < BN * BK / 4; i += 128) {
                int r = i >> 3, c = (i & 7) * 4;
                *(float4*)&Bs[r * (BK + 4) + c] =
                    *(const float4*)&Bp[(size_t)(n0 + r) * ldb + k0 + c];
            }
        } else {
            // B is [K,N] row-major; tile rows k0..k0+31, cols n0..n0+63
            #pragma unroll
            for (int i = tid; i < BK * BN / 4; i += 128) {
                int r = i >> 4, c = (i & 15) * 4;
                *(float4*)&Bs[r * (BN + 4) + c] =
                    *(const float4*)&Bp[(size_t)(k0 + r) * ldb + n0 + c];
            }
        }
        __syncthreads();

        #pragma unroll
        for (int kk = 0; kk < BK; kk += 8) {
            wmma::fragment<wmma::matrix_a, 16, 16, 8,
                           wmma::precision::tf32, wmma::row_major> af[2];
            #pragma unroll
            for (int im = 0; im < 2; im++) {
                wmma::load_matrix_sync(af[im], &As[wm + im * 16][kk], BK + 4);
                #pragma unroll
                for (int t = 0; t < af[im].num_elements; t++)
                    af[im].x[t] = wmma::__float_to_tf32(af[im].x[t]);
            }
            if constexpr (TRANS_B) {
                wmma::fragment<wmma::matrix_b, 16, 16, 8,
                               wmma::precision::tf32, wmma::col_major> bf[2];
                #pragma unroll
                for (int in = 0; in < 2; in++) {
                    wmma::load_matrix_sync(
                        bf[in], &Bs[(wn + in * 16) * (BK + 4) + kk], BK + 4);
                    #pragma unroll
                    for (int t = 0; t < bf[in].num_elements; t++)
                        bf[in].x[t] = wmma::__float_to_tf32(bf[in].x[t]);
                }
                #pragma unroll
                for (int im = 0; im < 2; im++)
                    #pragma unroll
                    for (int in = 0; in < 2; in++)
                        wmma::mma_sync(acc[im][in], af[im], bf[in], acc[im][in]);
            } else {
                wmma::fragment<wmma::matrix_b, 16, 16, 8,
                               wmma::precision::tf32, wmma::row_major> bf[2];
                #pragma unroll
                for (int in = 0; in < 2; in++) {
                    wmma::load_matrix_sync(
                        bf[in], &Bs[kk * (BN + 4) + wn + in * 16], BN + 4);
                    #pragma unroll
                    for (int t = 0; t < bf[in].num_elements; t++)
                        bf[in].x[t] = wmma::__float_to_tf32(bf[in].x[t]);
                }
                #pragma unroll
                for (int im = 0; im < 2; im++)
                    #pragma unroll
                    for (int in = 0; in < 2; in++)
                        wmma::mma_sync(acc[im][in], af[im], bf[in], acc[im][in]);
            }
        }
        __syncthreads();
    }

    #pragma unroll
    for (int im = 0; im < 2; im++)
        #pragma unroll
        for (int in = 0; in < 2; in++) {
            #pragma unroll
            for (int t = 0; t < acc[im][in].num_elements; t++)
                acc[im][in].x[t] *= alpha;
            wmma::store_matrix_sync(
                &Cp[(size_t)(m0 + wm + im * 16) * ldc + n0 + wn + in * 16],
                acc[im][in], ldc, wmma::mem_row_major);
        }
}

// ---------------------------------------------------------------------------
// Causal row softmax over S[B,T,T]: row i uses cols [0,i]; cols > i set to 0.
// One block of 256 threads per row.
// ---------------------------------------------------------------------------
__device__ __forceinline__ float blockReduce(float v, bool is_max)
{
    __shared__ float sh[33];
    __syncthreads();   // protect sh reuse across calls
    int lane = threadIdx.x & 31, wid = threadIdx.x >> 5;
    #pragma unroll
    for (int o = 16; o; o >>= 1) {
        float u = __shfl_xor_sync(0xFFFFFFFFu, v, o);
        v = is_max ? fmaxf(v, u) : (v + u);
    }
    if (lane == 0) sh[wid] = v;
    __syncthreads();
    if (wid == 0) {
        v = (lane < (blockDim.x >> 5)) ? sh[lane] : (is_max ? -INFINITY : 0.0f);
        #pragma unroll
        for (int o = 16; o; o >>= 1) {
            float u = __shfl_xor_sync(0xFFFFFFFFu, v, o);
            v = is_max ? fmaxf(v, u) : (v + u);
        }
        if (lane == 0) sh[32] = v;
    }
    __syncthreads();
    return sh[32];
}

__global__ void __launch_bounds__(256)
softmax_causal_kernel(float* __restrict__ S)
{
    const int row = blockIdx.x;            // 0..B*T-1 (batches contiguous)
    const int i   = row % T_;
    float* Srow = S + (size_t)row * T_;
    const int n = i + 1;

    float m = -INFINITY;
    for (int j = threadIdx.x; j < n; j += blockDim.x)
        m = fmaxf(m, Srow[j]);
    m = blockReduce(m, true);

    float s = 0.0f;
    for (int j = threadIdx.x; j < n; j += blockDim.x) {
        float e = __expf(Srow[j] - m);
        Srow[j] = e;
        s += e;
    }
    s = blockReduce(s, false);
    const float inv = 1.0f / s;

    for (int j = threadIdx.x; j < n; j += blockDim.x)
        Srow[j] *= inv;
    for (int j = n + threadIdx.x; j < T_; j += blockDim.x)
        Srow[j] = 0.0f;
}

// ---------------------------------------------------------------------------
// Launch
// ---------------------------------------------------------------------------
extern "C" void kernel_launch(void* const* d_in, const int* in_sizes, int n_in,
                              void* d_out, int out_size)
{
    const float* x     = (const float*)d_in[0];   // [B, T, C]
    const float* Wqkv  = (const float*)d_in[1];   // [C, 3C]
    const float* Wproj = (const float*)d_in[2];   // [C, C]
    float* out = (float*)d_out;                   // [B, T, C]

    static float* qkv = nullptr;
    static float* S   = nullptr;
    static float* O   = nullptr;
    if (!qkv) {
        cudaGetSymbolAddress((void**)&qkv, g_qkv);
        cudaGetSymbolAddress((void**)&S,   g_S);
        cudaGetSymbolAddress((void**)&O,   g_O);
    }

    const float scale = 1.0f / 32.0f;   // C^-0.5, C=1024
    dim3 blk(128);

    // 1. qkv = x @ Wqkv : [16384,1024] @ [1024,3072]
    {
        dim3 grid(N_QKV / BN, M_ROWS / BM, 1);
        gemm_tf32_kernel<false, 0><<<grid, blk>>>(
            x, Wqkv, qkv, M_ROWS, N_QKV, C_, C_, N_QKV, N_QKV,
            0, 0, 0, 1.0f);
    }

    // 2. S_b = Q_b @ K_b^T * scale (batched, causal block skip)
    {
        dim3 grid(T_ / BN, T_ / BM, B_);
        gemm_tf32_kernel<true, 1><<<grid, blk>>>(
            qkv /*Q at col 0*/, qkv + C_ /*K at col C*/, S,
            T_, T_, C_, N_QKV, N_QKV, T_,
            (long long)T_ * N_QKV, (long long)T_ * N_QKV, (long long)T_ * T_,
            scale);
    }

    // 3. causal softmax rows of S
    softmax_causal_kernel<<<M_ROWS, 256>>>(S);

    // 4. O_b = P_b @ V_b (batched, K-loop limited to diagonal)
    {
        dim3 grid(C_ / BN, T_ / BM, B_);
        gemm_tf32_kernel<false, 2><<<grid, blk>>>(
            S, qkv + 2 * C_ /*V at col 2C*/, O,
            T_, C_, T_, T_, N_QKV, C_,
            (long long)T_ * T_, (long long)T_ * N_QKV, (long long)T_ * C_,
            1.0f);
    }

    // 5. out = O @ Wproj : [16384,1024] @ [1024,1024]
    {
        dim3 grid(C_ / BN, M_ROWS / BM, 1);
        gemm_tf32_kernel<false, 0><<<grid, blk>>>(
            O, Wproj, out, M_ROWS, C_, C_, C_, C_, C_,
            0, 0, 0, 1.0f);
    }
}